// round 17
// baseline (speedup 1.0000x reference)
#include <cuda_runtime.h>
#include <cstdint>

#define NB    64
#define NT    1024
#define NIN   256
#define NH    512
#define NTHB  512
#define CLU   8                   // CTAs per cluster (col blocks)
#define NCLUS 16                  // clusters; each owns 4 batches (2 groups x 2)
#define NCTA  (NCLUS * CLU)       // 128

// SMEM float offsets (dynamic)
// frs[group g][buf b]: [512 k][4] dup-packed {b0,b0,b1,b1} -> 8KB each
#define FRS_BASE(g, b) (((g) * 2 + (b)) * 2048)
#define OFF_RED 8192              // red[2 seg]: [16 kt][2 b][80] floats each
#define RKT     160               // per-kt stride (2*80)
#define RBS     80                // per-batch stride (eb*80 mod 32 = {0,16}: conflict-free fold)
#define REDSZ   (16 * RKT)        // 2560 floats
#define SMEM_FLOATS (OFF_RED + 2 * REDSZ)
#define SMEM_BYTES  (SMEM_FLOATS * 4)     // 53,248 B
#define TXPEER  1024u             // per-producer tx: 64 cols x 16 B

// ---------------- helpers -----------------------------------------------------
__device__ __forceinline__ uint64_t pk2(float x, float y) {
    uint64_t d; asm("mov.b64 %0, {%1, %2};" : "=l"(d) : "f"(x), "f"(y)); return d;
}
__device__ __forceinline__ void upk2(uint64_t d, float& x, float& y) {
    asm("mov.b64 {%0, %1}, %2;" : "=f"(x), "=f"(y) : "l"(d));
}
__device__ __forceinline__ uint64_t fma2(uint64_t a, uint64_t b, uint64_t c) {
    uint64_t d; asm("fma.rn.f32x2 %0, %1, %2, %3;" : "=l"(d) : "l"(a), "l"(b), "l"(c)); return d;
}
__device__ __forceinline__ uint32_t sm_u32(const void* p) {
    return (uint32_t)__cvta_generic_to_shared(p);
}

#define MBAR_INIT(addr, cnt) \
    asm volatile("mbarrier.init.shared.b64 [%0], %1;" :: "r"(addr), "r"(cnt) : "memory")
#define ARRIVE_EXPECT(addr, tx) \
    asm volatile("mbarrier.arrive.expect_tx.shared.b64 _, [%0], %1;" :: "r"(addr), "r"(tx) : "memory")
#define WAITP(addr, ph) do {                                                    \
    uint32_t _done;                                                             \
    do {                                                                        \
        asm volatile("{\n\t.reg .pred p;\n\t"                                   \
            "mbarrier.try_wait.parity.acquire.cta.shared::cta.b64 p, [%1], %2, 0x989680;\n\t" \
            "selp.b32 %0, 1, 0, p;\n\t}"                                        \
            : "=r"(_done) : "r"(addr), "r"(ph) : "memory");                     \
    } while (!_done);                                                           \
} while (0)
#define ST_ASYNC16(raddr, v0, v1, rmbar) \
    asm volatile("st.async.weak.shared::cluster.mbarrier::complete_tx::bytes.v2.b64 " \
                 "[%0], {%1, %2}, [%3];" :: "r"(raddr), "l"(v0), "l"(v1), "r"(rmbar) : "memory")
#define MAPA(dst, src, r) \
    asm volatile("mapa.shared::cluster.u32 %0, %1, %2;" : "=r"(dst) : "r"(src), "r"(r))
#define CLUSTER_SYNC_() do {                                          \
    asm volatile("barrier.cluster.arrive.aligned;" ::: "memory");     \
    asm volatile("barrier.cluster.wait.aligned;" ::: "memory");       \
} while (0)

// ---------------- Phase A: v_in = x @ W_in + b_in -> d_out (FFMA2) -----------
#define BM 64
#define BN 64
#define BK 16

__global__ __launch_bounds__(256) void gemm_vin(const float* __restrict__ A,
                                                const float* __restrict__ Bm,
                                                const float* __restrict__ bias,
                                                float* __restrict__ C) {
    __shared__ float    As[BK][BM + 4];
    __shared__ uint64_t Bs2[BK][BN / 2];
    const int tid = threadIdx.x;
    const int m0 = blockIdx.y * BM;
    const int n0 = blockIdx.x * BN;
    const int tx = tid & 15;
    const int ty = tid >> 4;

    uint64_t acc[4][2];
#pragma unroll
    for (int i = 0; i < 4; ++i) { acc[i][0] = 0; acc[i][1] = 0; }

    for (int k0 = 0; k0 < NIN; k0 += BK) {
#pragma unroll
        for (int i = tid; i < BM * BK / 4; i += 256) {
            int m = i >> 2, kq = i & 3;
            float4 v = *(const float4*)(A + (long)(m0 + m) * NIN + k0 + kq * 4);
            As[kq * 4 + 0][m] = v.x;
            As[kq * 4 + 1][m] = v.y;
            As[kq * 4 + 2][m] = v.z;
            As[kq * 4 + 3][m] = v.w;
        }
#pragma unroll
        for (int i = tid; i < BK * BN / 4; i += 256) {
            int kk = i >> 4, nq = i & 15;
            float4 v = *(const float4*)(Bm + (long)(k0 + kk) * NH + n0 + nq * 4);
            Bs2[kk][nq * 2 + 0] = pk2(v.x, v.y);
            Bs2[kk][nq * 2 + 1] = pk2(v.z, v.w);
        }
        __syncthreads();

#pragma unroll
        for (int kk = 0; kk < BK; ++kk) {
            float4 a4 = *(const float4*)(&As[kk][ty * 4]);
            ulonglong2 bp = *(const ulonglong2*)(&Bs2[kk][tx * 2]);
            uint64_t ad0 = pk2(a4.x, a4.x);
            uint64_t ad1 = pk2(a4.y, a4.y);
            uint64_t ad2 = pk2(a4.z, a4.z);
            uint64_t ad3 = pk2(a4.w, a4.w);
            acc[0][0] = fma2(ad0, bp.x, acc[0][0]);
            acc[0][1] = fma2(ad0, bp.y, acc[0][1]);
            acc[1][0] = fma2(ad1, bp.x, acc[1][0]);
            acc[1][1] = fma2(ad1, bp.y, acc[1][1]);
            acc[2][0] = fma2(ad2, bp.x, acc[2][0]);
            acc[2][1] = fma2(ad2, bp.y, acc[2][1]);
            acc[3][0] = fma2(ad3, bp.x, acc[3][0]);
            acc[3][1] = fma2(ad3, bp.y, acc[3][1]);
        }
        __syncthreads();
    }

#pragma unroll
    for (int i = 0; i < 4; ++i) {
        const int m = m0 + ty * 4 + i;
        const int n = n0 + tx * 4;
        float c0, c1, c2, c3;
        upk2(acc[i][0], c0, c1);
        upk2(acc[i][1], c2, c3);
        float4 o;
        o.x = c0 + bias[n + 0];
        o.y = c1 + bias[n + 1];
        o.z = c2 + bias[n + 2];
        o.w = c3 + bias[n + 3];
        *(float4*)(C + (long)m * NH + n) = o;
    }
}

// ---------------- Phase B: persistent recurrent kernel ----------------------
// 16 clusters x 8 CTAs (128 SMs); cluster owns 4 batches = groups A/B (2 ea);
// CTA = 64 cols, W in REGISTERS (lane owns col-pair x 32 k = 32 u64).
// Each step runs segment A then B: A's exchange (drain+transit) hides under
// all of B. st.async + per-producer mbarriers, dup-packed sends, red
// double-buffered by segment, no tail sync.

__global__ __launch_bounds__(NTHB, 1) __cluster_dims__(CLU, 1, 1)
void step_kernel(const float* __restrict__ W_hid,
                 const float* __restrict__ b_hid,
                 const float* __restrict__ alpha,
                 const float* __restrict__ init_state,
                 float* __restrict__ out) {
    extern __shared__ float sh[];
    __shared__ uint64_t bars[2][2][CLU];   // [group][buf][producer rank]

    const int tid = threadIdx.x;
    uint32_t rank;
    asm("mov.u32 %0, %%cluster_ctarank;" : "=r"(rank));
    const int grp = blockIdx.x >> 3;       // 0..15 (batch super-group of 4)
    const int B0A = grp * 4;
    const int B0B = grp * 4 + 2;
    const int C0  = (int)rank * 64;

    const int kt     = tid >> 5;           // warp = k-slice (32 k)
    const int lane   = tid & 31;           // lane = col-pair
    const int myprod = kt >> 1;            // producer peer of my k-slice
    // fold roles (tid < 128): eb = batch (0/1), ec = col
    const int eb = tid & 1;
    const int ec = (tid >> 1) & 63;
    const int gc = C0 + ec;

    // ---- one-time: W col-pair slice into registers ----
    uint64_t wreg[32];
#pragma unroll
    for (int kk = 0; kk < 32; ++kk) {
        float2 wv = *(const float2*)(W_hid + (long)(kt * 32 + kk) * NH + C0 + 2 * lane);
        wreg[kk] = pk2(wv.x, wv.y);
    }

    // ---- barriers: 2 groups x 2 bufs x 8 producers; arm phase 0 w/ 1KB ----
    if (tid == 0) {
#pragma unroll
        for (int g = 0; g < 2; ++g)
#pragma unroll
            for (int bb = 0; bb < 2; ++bb)
#pragma unroll
                for (int r = 0; r < CLU; ++r) {
                    MBAR_INIT(sm_u32(&bars[g][bb][r]), 1);
                    ARRIVE_EXPECT(sm_u32(&bars[g][bb][r]), TXPEER);
                }
    }

    // ---- buf0 of both groups = relu(init_state), dup-packed [k][b0b0b1b1] ----
    for (int i = tid; i < NH * 4; i += NTHB) {
        int k = i >> 2, b = (i & 3) >> 1;
        sh[FRS_BASE(0, 0) + i] = fmaxf(init_state[(long)(B0A + b) * NH + k], 0.f);
        sh[FRS_BASE(1, 0) + i] = fmaxf(init_state[(long)(B0B + b) * NH + k], 0.f);
    }

    float vA = 0.f, vB = 0.f, al = 0.f, bh = 0.f, oma = 0.f;
    if (tid < 128) {
        vA  = init_state[(long)(B0A + eb) * NH + gc];
        vB  = init_state[(long)(B0B + eb) * NH + gc];
        al  = alpha[gc];
        bh  = b_hid[gc];
        oma = 1.f - al;
    }
    __syncthreads();
    CLUSTER_SYNC_();    // barriers + armed state visible before any st.async

    int phA0 = 0, phA1 = 0, phB0 = 0, phB1 = 0;

    // one segment: wait, compute, publish, sync, fold, send for group g
    auto segment = [&](int t, int g, int B0g, float& vG, int& phb0, int& phb1) {
        const int pb = (t - 1) & 1;        // buffer holding fr_g(t-1)
        const int b  = t & 1;              // buffer receiving fr_g(t)
        float* red = sh + OFF_RED + g * REDSZ;

        long  oidx = 0;
        float vin  = 0.f;
        if (tid < 128) {
            oidx = ((long)(B0g + eb) * NT + (t - 1)) * NH + gc;
            vin  = out[oidx];              // DRAM prefetch
        }

        if (t >= 2) {
            const uint32_t ba = sm_u32(&bars[g][pb][myprod]);
            const int ph = pb ? phb1 : phb0;
            WAITP(ba, ph);                 // my producer's 1KB landed
            if (pb) phb1 ^= 1; else phb0 ^= 1;
            if ((kt & 1) == 0 && lane == 0) ARRIVE_EXPECT(ba, TXPEER);
        }

        // ---- compute: per k: 1 broadcast LDS.128 + 2 FFMA2 (W in regs) ----
        const float* fbase = sh + FRS_BASE(g, pb) + kt * 128;
        uint64_t a0 = 0, a1 = 0;
#pragma unroll
        for (int kk = 0; kk < 32; ++kk) {
            ulonglong2 fv = *(const ulonglong2*)(fbase + kk * 4);  // {b0,b0},{b1,b1}
            a0 = fma2(fv.x, wreg[kk], a0);
            a1 = fma2(fv.y, wreg[kk], a1);
        }

        // ---- publish kt-partials into red[g] ----
        {
            float* rp = red + kt * RKT + 2 * lane;
            *(uint64_t*)(rp + 0 * RBS) = a0;
            *(uint64_t*)(rp + 1 * RBS) = a1;
        }
        __syncthreads();   // the ONLY per-segment CTA sync

        // ---- fold + leaky update + scatter fr_g(t) (warps 0-3) ----
        if (tid < 128) {
            const float* rr = red + eb * RBS + ec;
            float s0 = rr[0 * RKT]  + rr[1 * RKT];
            float s1 = rr[2 * RKT]  + rr[3 * RKT];
            float s2 = rr[4 * RKT]  + rr[5 * RKT];
            float s3 = rr[6 * RKT]  + rr[7 * RKT];
            float s4 = rr[8 * RKT]  + rr[9 * RKT];
            float s5 = rr[10 * RKT] + rr[11 * RKT];
            float s6 = rr[12 * RKT] + rr[13 * RKT];
            float s7 = rr[14 * RKT] + rr[15 * RKT];
            float s  = ((s0 + s1) + (s2 + s3)) + ((s4 + s5) + (s6 + s7));

            vG = oma * vG + al * (s + bh + vin);
            const float fr = fmaxf(vG, 0.f);

            if (t < NT) {                  // nobody consumes fr(NT)
                // width-2 shfl: lane pairs (2i, 2i+1) share ec
                const float g0 = __shfl_sync(0xffffffffu, fr, 0, 2);
                const float g1 = __shfl_sync(0xffffffffu, fr, 1, 2);
                if (eb == 0) {             // one sender per column
                    const uint64_t d0 = pk2(g0, g0);
                    const uint64_t d1 = pk2(g1, g1);
                    const uint32_t laddr =
                        sm_u32(sh + FRS_BASE(g, b) + gc * 4);
                    const uint32_t lbar = sm_u32(&bars[g][b][rank]);
#pragma unroll
                    for (int i = 0; i < CLU; ++i) {
                        const uint32_t r = (rank + (uint32_t)i) & 7;
                        uint32_t ra, rb;
                        MAPA(ra, laddr, r);
                        MAPA(rb, lbar, r);
                        ST_ASYNC16(ra, d0, d1, rb);
                    }
                }
            }
            out[oidx] = fr;                // off critical path
        }
        // no tail sync: red[g] WAR covered by the other segment's publish-sync
    };

    for (int t = 1; t <= NT; ++t) {
        segment(t, 0, B0A, vA, phA0, phA1);   // A's exchange hides under B
        segment(t, 1, B0B, vB, phB0, phB1);   // B's hides under next A
    }

    CLUSTER_SYNC_();                       // guard exit vs in-flight st.async
}

// ---------------- launch ----------------------------------------------------
extern "C" void kernel_launch(void* const* d_in, const int* in_sizes, int n_in,
                              void* d_out, int out_size) {
    const float* x     = (const float*)d_in[0];
    const float* init  = (const float*)d_in[1];
    const float* W_in  = (const float*)d_in[2];
    const float* b_in  = (const float*)d_in[3];
    const float* W_hid = (const float*)d_in[4];
    const float* b_hid = (const float*)d_in[5];
    const float* alpha = (const float*)d_in[6];
    float* out = (float*)d_out;

    cudaFuncSetAttribute(step_kernel,
                         cudaFuncAttributeMaxDynamicSharedMemorySize, SMEM_BYTES);

    dim3 grid(NH / BN, (NB * NT) / BM);    // (8, 1024)
    gemm_vin<<<grid, 256>>>(x, W_in, b_in, out);

    step_kernel<<<NCTA, NTHB, SMEM_BYTES>>>(W_hid, b_hid, alpha, init, out);
}